// round 14
// baseline (speedup 1.0000x reference)
#include <cuda_runtime.h>
#include <cuda_fp16.h>
#include <cstdint>

// Problem constants
#define BB 4
#define TT 2048
#define DD 1024
#define HH 16
#define HD 64
#define MM (BB * TT)   // 8192

#define LOG2E 1.44269504088896340736f

// fp16 tensors
__device__ __align__(16) __half g_x16[(size_t)MM * DD];
__device__ __align__(16) __half g_a16[(size_t)MM * DD];
__device__ __align__(16) __half g_q16[(size_t)MM * DD];   // pre-scaled by 0.125*log2(e)
__device__ __align__(16) __half g_k16[(size_t)MM * DD];
__device__ __align__(16) __half g_v16[(size_t)MM * DD];
__device__ __align__(16) __half g_w16[4][(size_t)DD * DD];   // Wq,Wk,Wv,Wp

// ---------------------------------------------------------------------------
// Merged fp32 -> fp16 convert: x + all 4 weights in ONE launch, 4-way ILP.
// ---------------------------------------------------------------------------
#define X4   (MM * DD / 4)
#define W4   (DD * DD / 4)          // == 1<<18
#define TOT4 (X4 + 4 * W4)

__global__ void cvt_all(const float* __restrict__ x,
                        const float* __restrict__ w0, const float* __restrict__ w1,
                        const float* __restrict__ w2, const float* __restrict__ w3)
{
    const int base = blockIdx.x * (256 * 4) + threadIdx.x;
#pragma unroll
    for (int j = 0; j < 4; ++j) {
        const int i = base + j * 256;
        const float* src;
        __half* dst;
        int off;
        if (i < X4) {
            src = x;  dst = g_x16;  off = i;
        } else {
            const int t = i - X4;
            const int s = t >> 18;
            off = t & (W4 - 1);
            src = (s == 0) ? w0 : (s == 1) ? w1 : (s == 2) ? w2 : w3;
            dst = g_w16[s];
        }
        const float4 v = ((const float4*)src)[off];
        *(__half2*)&dst[4 * (size_t)off]     = __floats2half2_rn(v.x, v.y);
        *(__half2*)&dst[4 * (size_t)off + 2] = __floats2half2_rn(v.z, v.w);
    }
}

// ---------------------------------------------------------------------------
// MMA / cp.async helpers
// ---------------------------------------------------------------------------
__device__ __forceinline__ uint32_t smem_u32(const void* p) {
    return (uint32_t)__cvta_generic_to_shared(p);
}
__device__ __forceinline__ void ldm_x4(uint32_t addr, uint32_t* r) {
    asm volatile("ldmatrix.sync.aligned.m8n8.x4.shared.b16 {%0,%1,%2,%3}, [%4];"
                 : "=r"(r[0]), "=r"(r[1]), "=r"(r[2]), "=r"(r[3]) : "r"(addr));
}
__device__ __forceinline__ void ldm_x4_t(uint32_t addr, uint32_t* r) {
    asm volatile("ldmatrix.sync.aligned.m8n8.x4.trans.shared.b16 {%0,%1,%2,%3}, [%4];"
                 : "=r"(r[0]), "=r"(r[1]), "=r"(r[2]), "=r"(r[3]) : "r"(addr));
}
__device__ __forceinline__ void mma_f16(float* c, const uint32_t* a, uint32_t b0, uint32_t b1) {
    asm volatile("mma.sync.aligned.m16n8k16.row.col.f32.f16.f16.f32 "
                 "{%0,%1,%2,%3}, {%4,%5,%6,%7}, {%8,%9}, {%0,%1,%2,%3};"
                 : "+f"(c[0]), "+f"(c[1]), "+f"(c[2]), "+f"(c[3])
                 : "r"(a[0]), "r"(a[1]), "r"(a[2]), "r"(a[3]), "r"(b0), "r"(b1));
}
__device__ __forceinline__ void cp16(uint32_t dst, const void* src) {
    asm volatile("cp.async.cg.shared.global [%0], [%1], 16;" :: "r"(dst), "l"(src));
}
__device__ __forceinline__ void cp_commit() {
    asm volatile("cp.async.commit_group;");
}
template <int N>
__device__ __forceinline__ void cp_wait() {
    asm volatile("cp.async.wait_group %0;" :: "n"(N));
}
__device__ __forceinline__ uint32_t ex2_f16x2(uint32_t x) {
    uint32_t r;
    asm("ex2.approx.f16x2 %0, %1;" : "=r"(r) : "r"(x));
    return r;
}

// ---------------------------------------------------------------------------
// fp16 NT GEMM (R10-best, FROZEN): block 128x128, 256 thr, warp tile 32x64,
// BK=64 (K=1024), 2-stage cp.async, one sync per K-iter, 2 CTAs/SM.
// mode 1 only here: fused QKV epilogue (fp16, Q*0.125*log2e)
// ---------------------------------------------------------------------------
#define GBK 64
#define GSST 72
#define GMAT (128 * GSST)
#define GSTAGE (2 * GMAT)
#define GEMM_SMEM (2 * GSTAGE * 2)   // 73728 bytes
#define GKITERS (DD / GBK)           // 16

__global__ __launch_bounds__(256, 2)
void gemm_qkv_f16()
{
    const __half* A = g_x16;
    const __half* W = g_w16[0];          // Wq,Wk,Wv contiguous

    extern __shared__ __half dsm[];

    const int tid  = threadIdx.x;
    const int warp = tid >> 5, lane = tid & 31;
    const int wm = warp >> 1, wn = warp & 1;
    const int m0 = blockIdx.y * 128, n0 = blockIdx.x * 128;

    const int lrow = tid >> 1;
    const int lcol = (tid & 1) * 32;
    const size_t gA = (size_t)(m0 + lrow) * DD + lcol;
    const size_t gW = (size_t)(n0 + lrow) * DD + lcol;
    const int soff = lrow * GSST + lcol;

#define G_ISSUE(it)                                                            \
    do {                                                                       \
        const int _k0 = (it) * GBK;                                            \
        __half* _s = dsm + ((it) & 1) * GSTAGE;                                \
        cp16(smem_u32(_s + soff),              A + gA + _k0);                  \
        cp16(smem_u32(_s + soff + 8),          A + gA + _k0 + 8);              \
        cp16(smem_u32(_s + soff + 16),         A + gA + _k0 + 16);             \
        cp16(smem_u32(_s + soff + 24),         A + gA + _k0 + 24);             \
        cp16(smem_u32(_s + GMAT + soff),       W + gW + _k0);                  \
        cp16(smem_u32(_s + GMAT + soff + 8),   W + gW + _k0 + 8);              \
        cp16(smem_u32(_s + GMAT + soff + 16),  W + gW + _k0 + 16);             \
        cp16(smem_u32(_s + GMAT + soff + 24),  W + gW + _k0 + 24);             \
    } while (0)

    float acc[2][8][4];
#pragma unroll
    for (int i = 0; i < 2; ++i)
#pragma unroll
        for (int j = 0; j < 8; ++j)
#pragma unroll
            for (int t = 0; t < 4; ++t) acc[i][j][t] = 0.f;

    G_ISSUE(0);  cp_commit();

#pragma unroll 2
    for (int it = 0; it < GKITERS; ++it) {
        cp_wait<0>();
        __syncthreads();
        if (it + 1 < GKITERS) {
            G_ISSUE(it + 1);
            cp_commit();
        }

        const __half* sA = dsm + (it & 1) * GSTAGE;
        const __half* sW = sA + GMAT;

#pragma unroll
        for (int ks = 0; ks < GBK; ks += 16) {
            uint32_t aF[2][4], bF[4][4];
            const int arow = wm * 32 + (lane & 15);
            const int acol = ks + ((lane >> 4) << 3);
#pragma unroll
            for (int mt = 0; mt < 2; ++mt)
                ldm_x4(smem_u32(&sA[(arow + mt * 16) * GSST + acol]), aF[mt]);
            const int brow = wn * 64 + ((lane >> 4) << 3) + (lane & 7);
            const int bcol = ks + ((lane >> 3) & 1) * 8;
#pragma unroll
            for (int nn = 0; nn < 4; ++nn)
                ldm_x4(smem_u32(&sW[(brow + nn * 16) * GSST + bcol]), bF[nn]);
#pragma unroll
            for (int mt = 0; mt < 2; ++mt)
#pragma unroll
                for (int nt = 0; nt < 8; ++nt) {
                    const int p = nt >> 1, q = (nt & 1) * 2;
                    mma_f16(acc[mt][nt], aF[mt], bF[p][q], bF[p][q + 1]);
                }
        }
    }
#undef G_ISSUE

#pragma unroll
    for (int mt = 0; mt < 2; ++mt) {
#pragma unroll
        for (int nt = 0; nt < 8; ++nt) {
            const int m = m0 + wm * 32 + mt * 16 + (lane >> 2);
            const int n = n0 + wn * 64 + nt * 8 + (lane & 3) * 2;
            const int arr = n >> 10;
            const int nc  = n & 1023;
            const float s = (arr == 0) ? (0.125f * LOG2E) : 1.f;
            __half* H = (arr == 0) ? g_q16 : (arr == 1) ? g_k16 : g_v16;
            __half2 v0 = __floats2half2_rn(acc[mt][nt][0] * s, acc[mt][nt][1] * s);
            __half2 v1 = __floats2half2_rn(acc[mt][nt][2] * s, acc[mt][nt][3] * s);
            *(__half2*)&H[(size_t)m * DD + nc]       = v0;
            *(__half2*)&H[(size_t)(m + 8) * DD + nc] = v1;
        }
    }
}

// ---------------------------------------------------------------------------
// Out-projection GEMM: tile 128(M)x64(N), warp tile 32x32, 256 thr, BK=64,
// 2-stage cp.async, 2 CTAs/SM. Grid 16x64 = 1024 blocks -> 3.46 waves
// (vs 1.73 for 128x128) to cut wave-quantization tail.
// ---------------------------------------------------------------------------
#define OMAT_W (64 * GSST)                   // W panel: 64 rows
#define OSTAGE (GMAT + OMAT_W)               // A(128 rows) + W(64 rows)
#define OGEMM_SMEM (2 * OSTAGE * 2)          // 55296 bytes

__global__ __launch_bounds__(256, 2)
void gemm_out_f16(const float* __restrict__ bias, float* __restrict__ Cout)
{
    const __half* A = g_a16;
    const __half* W = g_w16[3];

    extern __shared__ __half dsm[];

    const int tid  = threadIdx.x;
    const int warp = tid >> 5, lane = tid & 31;
    const int wm = warp >> 1, wn = warp & 1;       // 4 x 2 warps, 32x32 tiles
    const int m0 = blockIdx.y * 128, n0 = blockIdx.x * 64;

    const int lrow = tid >> 1;                      // 0..127
    const int lcol = (tid & 1) * 32;
    const size_t gA = (size_t)(m0 + lrow) * DD + lcol;
    // W: 64 rows, 2 chunks of 32 cols -> threads 0..127 cover it
    const int wrow = tid >> 1;                      // valid for tid < 128
    const size_t gW = (size_t)(n0 + (wrow & 63)) * DD + lcol;
    const int sAoff = lrow * GSST + lcol;
    const int sWoff = GMAT + (wrow & 63) * GSST + lcol;
    const bool doW = (tid < 128);

#define O_ISSUE(it)                                                            \
    do {                                                                       \
        const int _k0 = (it) * GBK;                                            \
        __half* _s = dsm + ((it) & 1) * OSTAGE;                                \
        cp16(smem_u32(_s + sAoff),              A + gA + _k0);                 \
        cp16(smem_u32(_s + sAoff + 8),          A + gA + _k0 + 8);             \
        cp16(smem_u32(_s + sAoff + 16),         A + gA + _k0 + 16);            \
        cp16(smem_u32(_s + sAoff + 24),         A + gA + _k0 + 24);            \
        if (doW) {                                                             \
            cp16(smem_u32(_s + sWoff),          W + gW + _k0);                 \
            cp16(smem_u32(_s + sWoff + 8),      W + gW + _k0 + 8);             \
            cp16(smem_u32(_s + sWoff + 16),     W + gW + _k0 + 16);            \
            cp16(smem_u32(_s + sWoff + 24),     W + gW + _k0 + 24);            \
        }                                                                      \
    } while (0)

    float acc[2][4][4];
#pragma unroll
    for (int i = 0; i < 2; ++i)
#pragma unroll
        for (int j = 0; j < 4; ++j)
#pragma unroll
            for (int t = 0; t < 4; ++t) acc[i][j][t] = 0.f;

    O_ISSUE(0);  cp_commit();

#pragma unroll 2
    for (int it = 0; it < GKITERS; ++it) {
        cp_wait<0>();
        __syncthreads();
        if (it + 1 < GKITERS) {
            O_ISSUE(it + 1);
            cp_commit();
        }

        const __half* sA = dsm + (it & 1) * OSTAGE;
        const __half* sW = sA + GMAT;

#pragma unroll
        for (int ks = 0; ks < GBK; ks += 16) {
            uint32_t aF[2][4], bF[2][4];
            const int arow = wm * 32 + (lane & 15);
            const int acol = ks + ((lane >> 4) << 3);
#pragma unroll
            for (int mt = 0; mt < 2; ++mt)
                ldm_x4(smem_u32(&sA[(arow + mt * 16) * GSST + acol]), aF[mt]);
            const int brow = wn * 32 + ((lane >> 4) << 3) + (lane & 7);
            const int bcol = ks + ((lane >> 3) & 1) * 8;
#pragma unroll
            for (int nn = 0; nn < 2; ++nn)
                ldm_x4(smem_u32(&sW[(brow + nn * 16) * GSST + bcol]), bF[nn]);
#pragma unroll
            for (int mt = 0; mt < 2; ++mt)
#pragma unroll
                for (int nt = 0; nt < 4; ++nt) {
                    const int p = nt >> 1, q = (nt & 1) * 2;
                    mma_f16(acc[mt][nt], aF[mt], bF[p][q], bF[p][q + 1]);
                }
        }
    }
#undef O_ISSUE

#pragma unroll
    for (int mt = 0; mt < 2; ++mt) {
#pragma unroll
        for (int nt = 0; nt < 4; ++nt) {
            const int m = m0 + wm * 32 + mt * 16 + (lane >> 2);
            const int n = n0 + wn * 32 + nt * 8 + (lane & 3) * 2;
            float b0 = bias[n], b1 = bias[n + 1];
            *(float2*)&Cout[(size_t)m * DD + n] =
                make_float2(acc[mt][nt][0] + b0, acc[mt][nt][1] + b1);
            *(float2*)&Cout[(size_t)(m + 8) * DD + n] =
                make_float2(acc[mt][nt][2] + b0, acc[mt][nt][3] + b1);
        }
    }
}

// ---------------------------------------------------------------------------
// fp16 causal flash attention (R12, FROZEN). 128-key double-buffered KV,
// base-2 f16x2 softmax, row-sums l via MMA.
// ---------------------------------------------------------------------------
#define H2_ONES 0x3C003C00u
#define FQ_ELEMS (128 * 72)
#define FKV_ELEMS (256 * 72)
#define FLASH_SMEM ((FQ_ELEMS + 2 * FKV_ELEMS) * 2)   // 92160 bytes

__global__ __launch_bounds__(256, 2)
void flash_attn_f16()
{
    const int qb = gridDim.x - 1 - blockIdx.x;
    const int h  = blockIdx.y;
    const int b  = blockIdx.z;
    const int tid  = threadIdx.x;
    const int warp = tid >> 5, lane = tid & 31;

    extern __shared__ __half fsm[];
    __half* smQ = fsm;
    __half* smKV0 = fsm + FQ_ELEMS;
    __half* smKV1 = smKV0 + FKV_ELEMS;

    const int q0 = qb * 128;
    const int qbase = q0 + warp * 16;
    const int nk = q0 + 128;

    {
        const size_t gk = ((size_t)(b * TT)) * DD + h * HD;
#pragma unroll
        for (int i = 0; i < 8; ++i) {
            int idx = tid + i * 256;
            int mat = idx >> 10;
            int w   = idx & 1023;
            int row = w >> 3;
            int col = (w & 7) * 8;
            const __half* src = mat ? g_v16 : g_k16;
            cp16(smem_u32(&smKV0[(mat * 128 + row) * 72 + col]),
                 &src[gk + (size_t)row * DD + col]);
        }
        cp_commit();
    }

    {
        const size_t g0 = ((size_t)(b * TT + q0)) * DD + h * HD;
#pragma unroll
        for (int i = 0; i < 4; ++i) {
            int idx = tid + i * 256;
            int row = idx >> 3;
            int col = (idx & 7) * 8;
            *(int4*)&smQ[row * 72 + col] =
                *(const int4*)&g_q16[g0 + (size_t)row * DD + col];
        }
    }
    __syncthreads();

    uint32_t aQ[4][4];
    {
        const int arow = warp * 16 + (lane & 15);
#pragma unroll
        for (int c = 0; c < 4; ++c) {
            const int acol = c * 16 + ((lane >> 4) << 3);
            ldm_x4(smem_u32(&smQ[arow * 72 + acol]), aQ[c]);
        }
    }

    float oacc[8][4];
#pragma unroll
    for (int nt = 0; nt < 8; ++nt)
#pragma unroll
        for (int t = 0; t < 4; ++t) oacc[nt][t] = 0.f;
    float lacc[4] = {0.f, 0.f, 0.f, 0.f};
    float m0 = 0.f, m1 = 0.f;

    const int r0i = qbase + (lane >> 2);
    const int r1i = r0i + 8;

    for (int kt = 0, buf = 0; kt < nk; kt += 128, buf ^= 1) {
        cp_wait<0>();
        __syncthreads();
        __half* smB = buf ? smKV1 : smKV0;

        if (kt + 128 < nk) {
            const size_t gk = ((size_t)(b * TT + kt + 128)) * DD + h * HD;
            __half* dst = buf ? smKV0 : smKV1;
#pragma unroll
            for (int i = 0; i < 8; ++i) {
                int idx = tid + i * 256;
                int mat = idx >> 10;
                int w   = idx & 1023;
                int row = w >> 3;
                int col = (w & 7) * 8;
                const __half* src = mat ? g_v16 : g_k16;
                cp16(smem_u32(&dst[(mat * 128 + row) * 72 + col]),
                     &src[gk + (size_t)row * DD + col]);
            }
            cp_commit();
        }

#pragma unroll
        for (int sub = 0; sub < 2; ++sub) {
            const int ks0 = kt + sub * 64;
            if (ks0 > qbase) break;

            const __half* smK = smB + (sub * 64) * 72;
            const __half* smV = smB + (128 + sub * 64) * 72;

            float sacc[8][4];
#pragma unroll
            for (int nt = 0; nt < 8; ++nt)
#pragma unroll
                for (int t = 0; t < 4; ++t) sacc[nt][t] = 0.f;

            const int brow = ((lane >> 4) << 3) + (lane & 7);
#pragma unroll
            for (int c = 0; c < 4; ++c) {
                uint32_t bK[4][4];
                const int bcol = c * 16 + ((lane >> 3) & 1) * 8;
#pragma unroll
                for (int p = 0; p < 4; ++p)
                    ldm_x4(smem_u32(&smK[(p * 16 + brow) * 72 + bcol]), bK[p]);
#pragma unroll
                for (int nt = 0; nt < 8; ++nt) {
                    const int p = nt >> 1, q = (nt & 1) * 2;
                    mma_f16(sacc[nt], aQ[c], bK[p][q], bK[p][q + 1]);
                }
            }

            if (ks0 + 63 > qbase) {
#pragma unroll
                for (int nt = 0; nt < 8; ++nt) {
                    const int cb = ks0 + nt * 8 + (lane & 3) * 2;
                    if (cb     > r0i) sacc[nt][0] = -1e30f;
                    if (cb + 1 > r0i) sacc[nt][1] = -1e30f;
                    if (cb     > r1i) sacc[nt][2] = -1e30f;
                    if (cb + 1 > r1i) sacc[nt][3] = -1e30f;
                }
            }

            float tm0 = -1e30f, tm1 = -1e30f;
#pragma unroll
            for (int nt = 0; nt < 8; ++nt) {
                tm0 = fmaxf(tm0, fmaxf(sacc[nt][0], sacc[nt][1]));
                tm1 = fmaxf(tm1, fmaxf(sacc[nt][2], sacc[nt][3]));
            }
            tm0 = fmaxf(tm0, __shfl_xor_sync(0xffffffffu, tm0, 1));
            tm0 = fmaxf(tm0, __shfl_xor_sync(0xffffffffu, tm0, 2));
            tm1 = fmaxf(tm1, __shfl_xor_sync(0xffffffffu, tm1, 1));
            tm1 = fmaxf(tm1, __shfl_xor_sync(0xffffffffu, tm1, 2));

            const float mn0 = fmaxf(m0, tm0), mn1 = fmaxf(m1, tm1);
            if (__ballot_sync(0xffffffffu, (mn0 > m0) | (mn1 > m1))) {
                const float c0 = exp2f(m0 - mn0), c1 = exp2f(m1 - mn1);
                lacc[0] *= c0; lacc[1] *= c0; lacc[2] *= c1; lacc[3] *= c1;
#pragma unroll
                for (int nt = 0; nt < 8; ++nt) {
                    oacc[nt][0] *= c0; oacc[nt][1] *= c0;
                    oacc[nt][2] *= c1; oacc[nt][3] *= c1;
                }
                m0 = mn0; m1 = mn1;
            }

            const __half2 mh0 = __float2half2_rn(m0);
            const __half2 mh1 = __float2half2_rn(m1);
            uint32_t aP[4][4];
#pragma unroll
            for (int nt = 0; nt < 8; ++nt) {
                __half2 s01 = __floats2half2_rn(sacc[nt][0], sacc[nt][1]);
                __half2 s23 = __floats2half2_rn(sacc[nt][2], sacc[nt][3]);
                s01 = __hsub2(s01, mh0);
                s23 = __hsub2(s23, mh1);
                const int c = nt >> 1, rr = (nt & 1) * 2;
                aP[c][rr]     = ex2_f16x2(reinterpret_cast<uint32_t&>(s01));
                aP[c][rr + 1] = ex2_f16x2(reinterpret_cast<uint32_t&>(s23));
            }

#pragma unroll
            for (int c = 0; c < 4; ++c) {
                uint32_t bV[8][2];
                const int vrow = c * 16 + ((lane >> 3) & 1) * 8 + (lane & 7);
                const int vcol0 = (lane >> 4) << 3;
#pragma unroll
                for (int pr = 0; pr < 4; ++pr) {
                    uint32_t r[4];
                    ldm_x4_t(smem_u32(&smV[vrow * 72 + 16 * pr + vcol0]), r);
                    bV[2 * pr][0] = r[0]; bV[2 * pr][1] = r[1];
                    bV[2 * pr + 1][0] = r[2]; bV[2 * pr + 1][1] = r[3];
                }
#pragma unroll
                for (int nt = 0; nt < 8; ++nt)
                    mma_f16(oacc[nt], aP[c], bV[nt][0], bV[nt][1]);
                mma_f16(lacc, aP[c], H2_ONES, H2_ONES);
            }
        }
    }

    const float inv0 = 1.f / lacc[0], inv1 = 1.f / lacc[2];

#pragma unroll
    for (int nt = 0; nt < 8; ++nt) {
        const int col = h * HD + nt * 8 + (lane & 3) * 2;
        const size_t o0 = ((size_t)(b * TT + r0i)) * DD + col;
        const size_t o1 = ((size_t)(b * TT + r1i)) * DD + col;
        *(__half2*)&g_a16[o0] = __floats2half2_rn(oacc[nt][0] * inv0, oacc[nt][1] * inv0);
        *(__half2*)&g_a16[o1] = __floats2half2_rn(oacc[nt][2] * inv1, oacc[nt][3] * inv1);
    }
}

// ---------------------------------------------------------------------------
// Launch: inputs per metadata order: x, Wk, Wq, Wv, Wp, bp
// ---------------------------------------------------------------------------
extern "C" void kernel_launch(void* const* d_in, const int* in_sizes, int n_in,
                              void* d_out, int out_size)
{
    const float* x  = (const float*)d_in[0];
    const float* Wk = (const float*)d_in[1];
    const float* Wq = (const float*)d_in[2];
    const float* Wv = (const float*)d_in[3];
    const float* Wp = (const float*)d_in[4];
    const float* bp = (const float*)d_in[5];
    float* out = (float*)d_out;

    cudaFuncSetAttribute(gemm_qkv_f16, cudaFuncAttributeMaxDynamicSharedMemorySize,
                         GEMM_SMEM);
    cudaFuncSetAttribute(gemm_out_f16, cudaFuncAttributeMaxDynamicSharedMemorySize,
                         OGEMM_SMEM);
    cudaFuncSetAttribute(flash_attn_f16, cudaFuncAttributeMaxDynamicSharedMemorySize,
                         FLASH_SMEM);

    // single merged convert (slot order: Wq, Wk, Wv, Wp)
    cvt_all<<<TOT4 / (256 * 4), 256>>>(x, Wq, Wk, Wv, Wp);

    // fused QKV projection: N = 3072
    dim3 qkvGrid(3 * DD / 128, MM / 128);   // 24 x 64
    gemm_qkv_f16<<<qkvGrid, 256, GEMM_SMEM>>>();

    // flash attention -> g_a16
    dim3 fGrid(TT / 128, HH, BB);           // 16 x 16 x 4
    flash_attn_f16<<<fGrid, 256, FLASH_SMEM>>>();

    // output projection with bias -> d_out (fp32), tile 128x64
    dim3 oGrid(DD / 64, MM / 128);          // 16 x 64 = 1024 blocks
    gemm_out_f16<<<oGrid, 256, OGEMM_SMEM>>>(bp, out);
}

// round 15
// speedup vs baseline: 1.0811x; 1.0811x over previous
#include <cuda_runtime.h>
#include <cuda_fp16.h>
#include <cstdint>

// Problem constants
#define BB 4
#define TT 2048
#define DD 1024
#define HH 16
#define HD 64
#define MM (BB * TT)   // 8192

#define LOG2E 1.44269504088896340736f

// fp16 tensors
__device__ __align__(16) __half g_x16[(size_t)MM * DD];
__device__ __align__(16) __half g_a16[(size_t)MM * DD];
__device__ __align__(16) __half g_q16[(size_t)MM * DD];   // pre-scaled by 0.125*log2(e)
__device__ __align__(16) __half g_k16[(size_t)MM * DD];
__device__ __align__(16) __half g_v16[(size_t)MM * DD];
__device__ __align__(16) __half g_w16[4][(size_t)DD * DD];   // Wq,Wk,Wv,Wp

// ---------------------------------------------------------------------------
// Merged fp32 -> fp16 convert: x + all 4 weights, ONE launch, 8-way ILP.
// ---------------------------------------------------------------------------
#define X4   (MM * DD / 4)
#define W4   (DD * DD / 4)          // == 1<<18
#define TOT4 (X4 + 4 * W4)          // 3145728

__global__ void cvt_all(const float* __restrict__ x,
                        const float* __restrict__ w0, const float* __restrict__ w1,
                        const float* __restrict__ w2, const float* __restrict__ w3)
{
    const int base = blockIdx.x * (256 * 8) + threadIdx.x;
#pragma unroll
    for (int j = 0; j < 8; ++j) {
        const int i = base + j * 256;
        const float* src;
        __half* dst;
        int off;
        if (i < X4) {
            src = x;  dst = g_x16;  off = i;
        } else {
            const int t = i - X4;
            const int s = t >> 18;
            off = t & (W4 - 1);
            src = (s == 0) ? w0 : (s == 1) ? w1 : (s == 2) ? w2 : w3;
            dst = g_w16[s];
        }
        const float4 v = ((const float4*)src)[off];
        *(__half2*)&dst[4 * (size_t)off]     = __floats2half2_rn(v.x, v.y);
        *(__half2*)&dst[4 * (size_t)off + 2] = __floats2half2_rn(v.z, v.w);
    }
}

// ---------------------------------------------------------------------------
// MMA / cp.async helpers
// ---------------------------------------------------------------------------
__device__ __forceinline__ uint32_t smem_u32(const void* p) {
    return (uint32_t)__cvta_generic_to_shared(p);
}
__device__ __forceinline__ void ldm_x4(uint32_t addr, uint32_t* r) {
    asm volatile("ldmatrix.sync.aligned.m8n8.x4.shared.b16 {%0,%1,%2,%3}, [%4];"
                 : "=r"(r[0]), "=r"(r[1]), "=r"(r[2]), "=r"(r[3]) : "r"(addr));
}
__device__ __forceinline__ void ldm_x4_t(uint32_t addr, uint32_t* r) {
    asm volatile("ldmatrix.sync.aligned.m8n8.x4.trans.shared.b16 {%0,%1,%2,%3}, [%4];"
                 : "=r"(r[0]), "=r"(r[1]), "=r"(r[2]), "=r"(r[3]) : "r"(addr));
}
__device__ __forceinline__ void mma_f16(float* c, const uint32_t* a, uint32_t b0, uint32_t b1) {
    asm volatile("mma.sync.aligned.m16n8k16.row.col.f32.f16.f16.f32 "
                 "{%0,%1,%2,%3}, {%4,%5,%6,%7}, {%8,%9}, {%0,%1,%2,%3};"
                 : "+f"(c[0]), "+f"(c[1]), "+f"(c[2]), "+f"(c[3])
                 : "r"(a[0]), "r"(a[1]), "r"(a[2]), "r"(a[3]), "r"(b0), "r"(b1));
}
__device__ __forceinline__ void cp16(uint32_t dst, const void* src) {
    asm volatile("cp.async.cg.shared.global [%0], [%1], 16;" :: "r"(dst), "l"(src));
}
__device__ __forceinline__ void cp16ca(uint32_t dst, const void* src) {
    asm volatile("cp.async.ca.shared.global [%0], [%1], 16;" :: "r"(dst), "l"(src));
}
__device__ __forceinline__ void cp_commit() {
    asm volatile("cp.async.commit_group;");
}
template <int N>
__device__ __forceinline__ void cp_wait() {
    asm volatile("cp.async.wait_group %0;" :: "n"(N));
}
__device__ __forceinline__ uint32_t ex2_f16x2(uint32_t x) {
    uint32_t r;
    asm("ex2.approx.f16x2 %0, %1;" : "=r"(r) : "r"(x));
    return r;
}

// ---------------------------------------------------------------------------
// fp16 NT GEMM (R10-best, FROZEN shape): block 128x128, 256 thr, warp 32x64,
// BK=64 (K=1024), 2-stage cp.async, one sync per K-iter, 2 CTAs/SM.
// A loads .ca (co-resident CTAs share the A panel -> L1 hits), W loads .cg.
// mode 0: fp32 out + bias.  mode 1: fused QKV epilogue (fp16, Q*0.125*log2e)
// ---------------------------------------------------------------------------
#define GBK 64
#define GSST 72
#define GMAT (128 * GSST)
#define GSTAGE (2 * GMAT)
#define GEMM_SMEM (2 * GSTAGE * 2)   // 73728 bytes
#define GKITERS (DD / GBK)           // 16

__global__ __launch_bounds__(256, 2)
void gemm_nt_f16(int aSel, int wSel, const float* __restrict__ bias,
                 float* __restrict__ Cout, int mode, int N)
{
    const __half* A = aSel ? g_a16 : g_x16;
    const __half* W = g_w16[wSel];

    extern __shared__ __half dsm[];

    const int tid  = threadIdx.x;
    const int warp = tid >> 5, lane = tid & 31;
    const int wm = warp >> 1, wn = warp & 1;
    const int m0 = blockIdx.y * 128, n0 = blockIdx.x * 128;

    const int lrow = tid >> 1;
    const int lcol = (tid & 1) * 32;
    const size_t gA = (size_t)(m0 + lrow) * DD + lcol;
    const size_t gW = (size_t)(n0 + lrow) * DD + lcol;
    const int soff = lrow * GSST + lcol;

#define G_ISSUE(it)                                                            \
    do {                                                                       \
        const int _k0 = (it) * GBK;                                            \
        __half* _s = dsm + ((it) & 1) * GSTAGE;                                \
        cp16ca(smem_u32(_s + soff),            A + gA + _k0);                  \
        cp16ca(smem_u32(_s + soff + 8),        A + gA + _k0 + 8);              \
        cp16ca(smem_u32(_s + soff + 16),       A + gA + _k0 + 16);             \
        cp16ca(smem_u32(_s + soff + 24),       A + gA + _k0 + 24);             \
        cp16(smem_u32(_s + GMAT + soff),       W + gW + _k0);                  \
        cp16(smem_u32(_s + GMAT + soff + 8),   W + gW + _k0 + 8);              \
        cp16(smem_u32(_s + GMAT + soff + 16),  W + gW + _k0 + 16);             \
        cp16(smem_u32(_s + GMAT + soff + 24),  W + gW + _k0 + 24);             \
    } while (0)

    float acc[2][8][4];
#pragma unroll
    for (int i = 0; i < 2; ++i)
#pragma unroll
        for (int j = 0; j < 8; ++j)
#pragma unroll
            for (int t = 0; t < 4; ++t) acc[i][j][t] = 0.f;

    G_ISSUE(0);  cp_commit();

#pragma unroll 2
    for (int it = 0; it < GKITERS; ++it) {
        cp_wait<0>();
        __syncthreads();
        if (it + 1 < GKITERS) {
            G_ISSUE(it + 1);
            cp_commit();
        }

        const __half* sA = dsm + (it & 1) * GSTAGE;
        const __half* sW = sA + GMAT;

#pragma unroll
        for (int ks = 0; ks < GBK; ks += 16) {
            uint32_t aF[2][4], bF[4][4];
            const int arow = wm * 32 + (lane & 15);
            const int acol = ks + ((lane >> 4) << 3);
#pragma unroll
            for (int mt = 0; mt < 2; ++mt)
                ldm_x4(smem_u32(&sA[(arow + mt * 16) * GSST + acol]), aF[mt]);
            const int brow = wn * 64 + ((lane >> 4) << 3) + (lane & 7);
            const int bcol = ks + ((lane >> 3) & 1) * 8;
#pragma unroll
            for (int nn = 0; nn < 4; ++nn)
                ldm_x4(smem_u32(&sW[(brow + nn * 16) * GSST + bcol]), bF[nn]);
#pragma unroll
            for (int mt = 0; mt < 2; ++mt)
#pragma unroll
                for (int nt = 0; nt < 8; ++nt) {
                    const int p = nt >> 1, q = (nt & 1) * 2;
                    mma_f16(acc[mt][nt], aF[mt], bF[p][q], bF[p][q + 1]);
                }
        }
    }
#undef G_ISSUE

#pragma unroll
    for (int mt = 0; mt < 2; ++mt) {
#pragma unroll
        for (int nt = 0; nt < 8; ++nt) {
            const int m = m0 + wm * 32 + mt * 16 + (lane >> 2);
            const int n = n0 + wn * 64 + nt * 8 + (lane & 3) * 2;
            if (mode == 0) {
                float b0 = bias[n], b1 = bias[n + 1];
                *(float2*)&Cout[(size_t)m * N + n] =
                    make_float2(acc[mt][nt][0] + b0, acc[mt][nt][1] + b1);
                *(float2*)&Cout[(size_t)(m + 8) * N + n] =
                    make_float2(acc[mt][nt][2] + b0, acc[mt][nt][3] + b1);
            } else {
                const int arr = n >> 10;
                const int nc  = n & 1023;
                const float s = (arr == 0) ? (0.125f * LOG2E) : 1.f;
                __half* H = (arr == 0) ? g_q16 : (arr == 1) ? g_k16 : g_v16;
                __half2 v0 = __floats2half2_rn(acc[mt][nt][0] * s, acc[mt][nt][1] * s);
                __half2 v1 = __floats2half2_rn(acc[mt][nt][2] * s, acc[mt][nt][3] * s);
                *(__half2*)&H[(size_t)m * DD + nc]       = v0;
                *(__half2*)&H[(size_t)(m + 8) * DD + nc] = v1;
            }
        }
    }
}

// ---------------------------------------------------------------------------
// fp16 causal flash attention (R12-best, FROZEN). 128-key double-buffered KV,
// base-2 f16x2 softmax, row-sums l via MMA.
// ---------------------------------------------------------------------------
#define H2_ONES 0x3C003C00u
#define FQ_ELEMS (128 * 72)
#define FKV_ELEMS (256 * 72)
#define FLASH_SMEM ((FQ_ELEMS + 2 * FKV_ELEMS) * 2)   // 92160 bytes

__global__ __launch_bounds__(256, 2)
void flash_attn_f16()
{
    const int qb = gridDim.x - 1 - blockIdx.x;
    const int h  = blockIdx.y;
    const int b  = blockIdx.z;
    const int tid  = threadIdx.x;
    const int warp = tid >> 5, lane = tid & 31;

    extern __shared__ __half fsm[];
    __half* smQ = fsm;
    __half* smKV0 = fsm + FQ_ELEMS;
    __half* smKV1 = smKV0 + FKV_ELEMS;

    const int q0 = qb * 128;
    const int qbase = q0 + warp * 16;
    const int nk = q0 + 128;

    {
        const size_t gk = ((size_t)(b * TT)) * DD + h * HD;
#pragma unroll
        for (int i = 0; i < 8; ++i) {
            int idx = tid + i * 256;
            int mat = idx >> 10;
            int w   = idx & 1023;
            int row = w >> 3;
            int col = (w & 7) * 8;
            const __half* src = mat ? g_v16 : g_k16;
            cp16(smem_u32(&smKV0[(mat * 128 + row) * 72 + col]),
                 &src[gk + (size_t)row * DD + col]);
        }
        cp_commit();
    }

    {
        const size_t g0 = ((size_t)(b * TT + q0)) * DD + h * HD;
#pragma unroll
        for (int i = 0; i < 4; ++i) {
            int idx = tid + i * 256;
            int row = idx >> 3;
            int col = (idx & 7) * 8;
            *(int4*)&smQ[row * 72 + col] =
                *(const int4*)&g_q16[g0 + (size_t)row * DD + col];
        }
    }
    __syncthreads();

    uint32_t aQ[4][4];
    {
        const int arow = warp * 16 + (lane & 15);
#pragma unroll
        for (int c = 0; c < 4; ++c) {
            const int acol = c * 16 + ((lane >> 4) << 3);
            ldm_x4(smem_u32(&smQ[arow * 72 + acol]), aQ[c]);
        }
    }

    float oacc[8][4];
#pragma unroll
    for (int nt = 0; nt < 8; ++nt)
#pragma unroll
        for (int t = 0; t < 4; ++t) oacc[nt][t] = 0.f;
    float lacc[4] = {0.f, 0.f, 0.f, 0.f};
    float m0 = 0.f, m1 = 0.f;

    const int r0i = qbase + (lane >> 2);
    const int r1i = r0i + 8;

    for (int kt = 0, buf = 0; kt < nk; kt += 128, buf ^= 1) {
        cp_wait<0>();
        __syncthreads();
        __half* smB = buf ? smKV1 : smKV0;

        if (kt + 128 < nk) {
            const size_t gk = ((size_t)(b * TT + kt + 128)) * DD + h * HD;
            __half* dst = buf ? smKV0 : smKV1;
#pragma unroll
            for (int i = 0; i < 8; ++i) {
                int idx = tid + i * 256;
                int mat = idx >> 10;
                int w   = idx & 1023;
                int row = w >> 3;
                int col = (w & 7) * 8;
                const __half* src = mat ? g_v16 : g_k16;
                cp16(smem_u32(&dst[(mat * 128 + row) * 72 + col]),
                     &src[gk + (size_t)row * DD + col]);
            }
            cp_commit();
        }

#pragma unroll
        for (int sub = 0; sub < 2; ++sub) {
            const int ks0 = kt + sub * 64;
            if (ks0 > qbase) break;

            const __half* smK = smB + (sub * 64) * 72;
            const __half* smV = smB + (128 + sub * 64) * 72;

            float sacc[8][4];
#pragma unroll
            for (int nt = 0; nt < 8; ++nt)
#pragma unroll
                for (int t = 0; t < 4; ++t) sacc[nt][t] = 0.f;

            const int brow = ((lane >> 4) << 3) + (lane & 7);
#pragma unroll
            for (int c = 0; c < 4; ++c) {
                uint32_t bK[4][4];
                const int bcol = c * 16 + ((lane >> 3) & 1) * 8;
#pragma unroll
                for (int p = 0; p < 4; ++p)
                    ldm_x4(smem_u32(&smK[(p * 16 + brow) * 72 + bcol]), bK[p]);
#pragma unroll
                for (int nt = 0; nt < 8; ++nt) {
                    const int p = nt >> 1, q = (nt & 1) * 2;
                    mma_f16(sacc[nt], aQ[c], bK[p][q], bK[p][q + 1]);
                }
            }

            if (ks0 + 63 > qbase) {
#pragma unroll
                for (int nt = 0; nt < 8; ++nt) {
                    const int cb = ks0 + nt * 8 + (lane & 3) * 2;
                    if (cb     > r0i) sacc[nt][0] = -1e30f;
                    if (cb + 1 > r0i) sacc[nt][1] = -1e30f;
                    if (cb     > r1i) sacc[nt][2] = -1e30f;
                    if (cb + 1 > r1i) sacc[nt][3] = -1e30f;
                }
            }

            float tm0 = -1e30f, tm1 = -1e30f;
#pragma unroll
            for (int nt = 0; nt < 8; ++nt) {
                tm0 = fmaxf(tm0, fmaxf(sacc[nt][0], sacc[nt][1]));
                tm1 = fmaxf(tm1, fmaxf(sacc[nt][2], sacc[nt][3]));
            }
            tm0 = fmaxf(tm0, __shfl_xor_sync(0xffffffffu, tm0, 1));
            tm0 = fmaxf(tm0, __shfl_xor_sync(0xffffffffu, tm0, 2));
            tm1 = fmaxf(tm1, __shfl_xor_sync(0xffffffffu, tm1, 1));
            tm1 = fmaxf(tm1, __shfl_xor_sync(0xffffffffu, tm1, 2));

            const float mn0 = fmaxf(m0, tm0), mn1 = fmaxf(m1, tm1);
            if (__ballot_sync(0xffffffffu, (mn0 > m0) | (mn1 > m1))) {
                const float c0 = exp2f(m0 - mn0), c1 = exp2f(m1 - mn1);
                lacc[0] *= c0; lacc[1] *= c0; lacc[2] *= c1; lacc[3] *= c1;
#pragma unroll
                for (int nt = 0; nt < 8; ++nt) {
                    oacc[nt][0] *= c0; oacc[nt][1] *= c0;
                    oacc[nt][2] *= c1; oacc[nt][3] *= c1;
                }
                m0 = mn0; m1 = mn1;
            }

            const __half2 mh0 = __float2half2_rn(m0);
            const __half2 mh1 = __float2half2_rn(m1);
            uint32_t aP[4][4];
#pragma unroll
            for (int nt = 0; nt < 8; ++nt) {
                __half2 s01 = __floats2half2_rn(sacc[nt][0], sacc[nt][1]);
                __half2 s23 = __floats2half2_rn(sacc[nt][2], sacc[nt][3]);
                s01 = __hsub2(s01, mh0);
                s23 = __hsub2(s23, mh1);
                const int c = nt >> 1, rr = (nt & 1) * 2;
                aP[c][rr]     = ex2_f16x2(reinterpret_cast<uint32_t&>(s01));
                aP[c][rr + 1] = ex2_f16x2(reinterpret_cast<uint32_t&>(s23));
            }

#pragma unroll
            for (int c = 0; c < 4; ++c) {
                uint32_t bV[8][2];
                const int vrow = c * 16 + ((lane >> 3) & 1) * 8 + (lane & 7);
                const int vcol0 = (lane >> 4) << 3;
#pragma unroll
                for (int pr = 0; pr < 4; ++pr) {
                    uint32_t r[4];
                    ldm_x4_t(smem_u32(&smV[vrow * 72 + 16 * pr + vcol0]), r);
                    bV[2 * pr][0] = r[0]; bV[2 * pr][1] = r[1];
                    bV[2 * pr + 1][0] = r[2]; bV[2 * pr + 1][1] = r[3];
                }
#pragma unroll
                for (int nt = 0; nt < 8; ++nt)
                    mma_f16(oacc[nt], aP[c], bV[nt][0], bV[nt][1]);
                mma_f16(lacc, aP[c], H2_ONES, H2_ONES);
            }
        }
    }

    const float inv0 = 1.f / lacc[0], inv1 = 1.f / lacc[2];

#pragma unroll
    for (int nt = 0; nt < 8; ++nt) {
        const int col = h * HD + nt * 8 + (lane & 3) * 2;
        const size_t o0 = ((size_t)(b * TT + r0i)) * DD + col;
        const size_t o1 = ((size_t)(b * TT + r1i)) * DD + col;
        *(__half2*)&g_a16[o0] = __floats2half2_rn(oacc[nt][0] * inv0, oacc[nt][1] * inv0);
        *(__half2*)&g_a16[o1] = __floats2half2_rn(oacc[nt][2] * inv1, oacc[nt][3] * inv1);
    }
}

// ---------------------------------------------------------------------------
// Launch: inputs per metadata order: x, Wk, Wq, Wv, Wp, bp
// ---------------------------------------------------------------------------
extern "C" void kernel_launch(void* const* d_in, const int* in_sizes, int n_in,
                              void* d_out, int out_size)
{
    const float* x  = (const float*)d_in[0];
    const float* Wk = (const float*)d_in[1];
    const float* Wq = (const float*)d_in[2];
    const float* Wv = (const float*)d_in[3];
    const float* Wp = (const float*)d_in[4];
    const float* bp = (const float*)d_in[5];
    float* out = (float*)d_out;

    cudaFuncSetAttribute(gemm_nt_f16, cudaFuncAttributeMaxDynamicSharedMemorySize,
                         GEMM_SMEM);
    cudaFuncSetAttribute(flash_attn_f16, cudaFuncAttributeMaxDynamicSharedMemorySize,
                         FLASH_SMEM);

    // single merged convert (slot order: Wq, Wk, Wv, Wp), 8-way ILP
    cvt_all<<<TOT4 / (256 * 8), 256>>>(x, Wq, Wk, Wv, Wp);

    // fused QKV projection: N = 3072
    dim3 qkvGrid(3 * DD / 128, MM / 128);   // 24 x 64
    gemm_nt_f16<<<qkvGrid, 256, GEMM_SMEM>>>(0, 0, nullptr, nullptr, 1, 3 * DD);

    // flash attention -> g_a16
    dim3 fGrid(TT / 128, HH, BB);           // 16 x 16 x 4
    flash_attn_f16<<<fGrid, 256, FLASH_SMEM>>>();

    // output projection with bias -> d_out (fp32)
    dim3 oGrid(DD / 128, MM / 128);         // 8 x 64
    gemm_nt_f16<<<oGrid, 256, GEMM_SMEM>>>(1, 3, bp, out, 0, DD);
}

// round 16
// speedup vs baseline: 1.0856x; 1.0042x over previous
#include <cuda_runtime.h>
#include <cuda_fp16.h>
#include <cstdint>

// Problem constants
#define BB 4
#define TT 2048
#define DD 1024
#define HH 16
#define HD 64
#define MM (BB * TT)   // 8192

#define LOG2E 1.44269504088896340736f

// fp16 tensors
__device__ __align__(16) __half g_x16[(size_t)MM * DD];
__device__ __align__(16) __half g_a16[(size_t)MM * DD];
__device__ __align__(16) __half g_q16[(size_t)MM * DD];   // pre-scaled by 0.125*log2(e)
__device__ __align__(16) __half g_k16[(size_t)MM * DD];
__device__ __align__(16) __half g_v16[(size_t)MM * DD];
__device__ __align__(16) __half g_w16[4][(size_t)DD * DD];   // Wq,Wk,Wv,Wp

// ---------------------------------------------------------------------------
// Merged fp32 -> fp16 convert: x + all 4 weights, ONE launch, 8-way ILP.
// ---------------------------------------------------------------------------
#define X4   (MM * DD / 4)
#define W4   (DD * DD / 4)          // == 1<<18
#define TOT4 (X4 + 4 * W4)          // 3145728

__global__ void cvt_all(const float* __restrict__ x,
                        const float* __restrict__ w0, const float* __restrict__ w1,
                        const float* __restrict__ w2, const float* __restrict__ w3)
{
    const int base = blockIdx.x * (256 * 8) + threadIdx.x;
#pragma unroll
    for (int j = 0; j < 8; ++j) {
        const int i = base + j * 256;
        const float* src;
        __half* dst;
        int off;
        if (i < X4) {
            src = x;  dst = g_x16;  off = i;
        } else {
            const int t = i - X4;
            const int s = t >> 18;
            off = t & (W4 - 1);
            src = (s == 0) ? w0 : (s == 1) ? w1 : (s == 2) ? w2 : w3;
            dst = g_w16[s];
        }
        const float4 v = ((const float4*)src)[off];
        *(__half2*)&dst[4 * (size_t)off]     = __floats2half2_rn(v.x, v.y);
        *(__half2*)&dst[4 * (size_t)off + 2] = __floats2half2_rn(v.z, v.w);
    }
}

// ---------------------------------------------------------------------------
// MMA / cp.async helpers
// ---------------------------------------------------------------------------
__device__ __forceinline__ uint32_t smem_u32(const void* p) {
    return (uint32_t)__cvta_generic_to_shared(p);
}
__device__ __forceinline__ void ldm_x4(uint32_t addr, uint32_t* r) {
    asm volatile("ldmatrix.sync.aligned.m8n8.x4.shared.b16 {%0,%1,%2,%3}, [%4];"
                 : "=r"(r[0]), "=r"(r[1]), "=r"(r[2]), "=r"(r[3]) : "r"(addr));
}
__device__ __forceinline__ void ldm_x4_t(uint32_t addr, uint32_t* r) {
    asm volatile("ldmatrix.sync.aligned.m8n8.x4.trans.shared.b16 {%0,%1,%2,%3}, [%4];"
                 : "=r"(r[0]), "=r"(r[1]), "=r"(r[2]), "=r"(r[3]) : "r"(addr));
}
__device__ __forceinline__ void mma_f16(float* c, const uint32_t* a, uint32_t b0, uint32_t b1) {
    asm volatile("mma.sync.aligned.m16n8k16.row.col.f32.f16.f16.f32 "
                 "{%0,%1,%2,%3}, {%4,%5,%6,%7}, {%8,%9}, {%0,%1,%2,%3};"
                 : "+f"(c[0]), "+f"(c[1]), "+f"(c[2]), "+f"(c[3])
                 : "r"(a[0]), "r"(a[1]), "r"(a[2]), "r"(a[3]), "r"(b0), "r"(b1));
}
__device__ __forceinline__ void cp16(uint32_t dst, const void* src) {
    asm volatile("cp.async.cg.shared.global [%0], [%1], 16;" :: "r"(dst), "l"(src));
}
__device__ __forceinline__ void cp16ca(uint32_t dst, const void* src) {
    asm volatile("cp.async.ca.shared.global [%0], [%1], 16;" :: "r"(dst), "l"(src));
}
__device__ __forceinline__ void cp_commit() {
    asm volatile("cp.async.commit_group;");
}
template <int N>
__device__ __forceinline__ void cp_wait() {
    asm volatile("cp.async.wait_group %0;" :: "n"(N));
}
__device__ __forceinline__ uint32_t ex2_f16x2(uint32_t x) {
    uint32_t r;
    asm("ex2.approx.f16x2 %0, %1;" : "=r"(r) : "r"(x));
    return r;
}

// ---------------------------------------------------------------------------
// fp16 NT GEMM (R14-best, FROZEN): block 128x128, 256 thr, warp 32x64,
// BK=64 (K=1024), 2-stage cp.async, one sync per K-iter, 2 CTAs/SM.
// A loads .ca (co-resident CTAs share the A panel -> L1 hits), W loads .cg.
// mode 0: fp32 out + bias.  mode 1: fused QKV epilogue (fp16, Q*0.125*log2e)
// ---------------------------------------------------------------------------
#define GBK 64
#define GSST 72
#define GMAT (128 * GSST)
#define GSTAGE (2 * GMAT)
#define GEMM_SMEM (2 * GSTAGE * 2)   // 73728 bytes
#define GKITERS (DD / GBK)           // 16

__global__ __launch_bounds__(256, 2)
void gemm_nt_f16(int aSel, int wSel, const float* __restrict__ bias,
                 float* __restrict__ Cout, int mode, int N)
{
    const __half* A = aSel ? g_a16 : g_x16;
    const __half* W = g_w16[wSel];

    extern __shared__ __half dsm[];

    const int tid  = threadIdx.x;
    const int warp = tid >> 5, lane = tid & 31;
    const int wm = warp >> 1, wn = warp & 1;
    const int m0 = blockIdx.y * 128, n0 = blockIdx.x * 128;

    const int lrow = tid >> 1;
    const int lcol = (tid & 1) * 32;
    const size_t gA = (size_t)(m0 + lrow) * DD + lcol;
    const size_t gW = (size_t)(n0 + lrow) * DD + lcol;
    const int soff = lrow * GSST + lcol;

#define G_ISSUE(it)                                                            \
    do {                                                                       \
        const int _k0 = (it) * GBK;                                            \
        __half* _s = dsm + ((it) & 1) * GSTAGE;                                \
        cp16ca(smem_u32(_s + soff),            A + gA + _k0);                  \
        cp16ca(smem_u32(_s + soff + 8),        A + gA + _k0 + 8);              \
        cp16ca(smem_u32(_s + soff + 16),       A + gA + _k0 + 16);             \
        cp16ca(smem_u32(_s + soff + 24),       A + gA + _k0 + 24);             \
        cp16(smem_u32(_s + GMAT + soff),       W + gW + _k0);                  \
        cp16(smem_u32(_s + GMAT + soff + 8),   W + gW + _k0 + 8);              \
        cp16(smem_u32(_s + GMAT + soff + 16),  W + gW + _k0 + 16);             \
        cp16(smem_u32(_s + GMAT + soff + 24),  W + gW + _k0 + 24);             \
    } while (0)

    float acc[2][8][4];
#pragma unroll
    for (int i = 0; i < 2; ++i)
#pragma unroll
        for (int j = 0; j < 8; ++j)
#pragma unroll
            for (int t = 0; t < 4; ++t) acc[i][j][t] = 0.f;

    G_ISSUE(0);  cp_commit();

#pragma unroll 2
    for (int it = 0; it < GKITERS; ++it) {
        cp_wait<0>();
        __syncthreads();
        if (it + 1 < GKITERS) {
            G_ISSUE(it + 1);
            cp_commit();
        }

        const __half* sA = dsm + (it & 1) * GSTAGE;
        const __half* sW = sA + GMAT;

#pragma unroll
        for (int ks = 0; ks < GBK; ks += 16) {
            uint32_t aF[2][4], bF[4][4];
            const int arow = wm * 32 + (lane & 15);
            const int acol = ks + ((lane >> 4) << 3);
#pragma unroll
            for (int mt = 0; mt < 2; ++mt)
                ldm_x4(smem_u32(&sA[(arow + mt * 16) * GSST + acol]), aF[mt]);
            const int brow = wn * 64 + ((lane >> 4) << 3) + (lane & 7);
            const int bcol = ks + ((lane >> 3) & 1) * 8;
#pragma unroll
            for (int nn = 0; nn < 4; ++nn)
                ldm_x4(smem_u32(&sW[(brow + nn * 16) * GSST + bcol]), bF[nn]);
#pragma unroll
            for (int mt = 0; mt < 2; ++mt)
#pragma unroll
                for (int nt = 0; nt < 8; ++nt) {
                    const int p = nt >> 1, q = (nt & 1) * 2;
                    mma_f16(acc[mt][nt], aF[mt], bF[p][q], bF[p][q + 1]);
                }
        }
    }
#undef G_ISSUE

#pragma unroll
    for (int mt = 0; mt < 2; ++mt) {
#pragma unroll
        for (int nt = 0; nt < 8; ++nt) {
            const int m = m0 + wm * 32 + mt * 16 + (lane >> 2);
            const int n = n0 + wn * 64 + nt * 8 + (lane & 3) * 2;
            if (mode == 0) {
                float b0 = bias[n], b1 = bias[n + 1];
                *(float2*)&Cout[(size_t)m * N + n] =
                    make_float2(acc[mt][nt][0] + b0, acc[mt][nt][1] + b1);
                *(float2*)&Cout[(size_t)(m + 8) * N + n] =
                    make_float2(acc[mt][nt][2] + b0, acc[mt][nt][3] + b1);
            } else {
                const int arr = n >> 10;
                const int nc  = n & 1023;
                const float s = (arr == 0) ? (0.125f * LOG2E) : 1.f;
                __half* H = (arr == 0) ? g_q16 : (arr == 1) ? g_k16 : g_v16;
                __half2 v0 = __floats2half2_rn(acc[mt][nt][0] * s, acc[mt][nt][1] * s);
                __half2 v1 = __floats2half2_rn(acc[mt][nt][2] * s, acc[mt][nt][3] * s);
                *(__half2*)&H[(size_t)m * DD + nc]       = v0;
                *(__half2*)&H[(size_t)(m + 8) * DD + nc] = v1;
            }
        }
    }
}

// ---------------------------------------------------------------------------
// fp16 causal flash attention (R12 structure). 128-key double-buffered KV,
// base-2 f16x2 softmax, row-sums l via MMA.
// NEW: KV + Q staged with cp.async.ca — co-resident CTAs (adjacent qb, same
// (b,h)) stream the same K/V, so the trailing CTA hits L1.
// ---------------------------------------------------------------------------
#define H2_ONES 0x3C003C00u
#define FQ_ELEMS (128 * 72)
#define FKV_ELEMS (256 * 72)
#define FLASH_SMEM ((FQ_ELEMS + 2 * FKV_ELEMS) * 2)   // 92160 bytes

__global__ __launch_bounds__(256, 2)
void flash_attn_f16()
{
    const int qb = gridDim.x - 1 - blockIdx.x;
    const int h  = blockIdx.y;
    const int b  = blockIdx.z;
    const int tid  = threadIdx.x;
    const int warp = tid >> 5, lane = tid & 31;

    extern __shared__ __half fsm[];
    __half* smQ = fsm;
    __half* smKV0 = fsm + FQ_ELEMS;
    __half* smKV1 = smKV0 + FKV_ELEMS;

    const int q0 = qb * 128;
    const int qbase = q0 + warp * 16;
    const int nk = q0 + 128;

    {
        const size_t gk = ((size_t)(b * TT)) * DD + h * HD;
#pragma unroll
        for (int i = 0; i < 8; ++i) {
            int idx = tid + i * 256;
            int mat = idx >> 10;
            int w   = idx & 1023;
            int row = w >> 3;
            int col = (w & 7) * 8;
            const __half* src = mat ? g_v16 : g_k16;
            cp16ca(smem_u32(&smKV0[(mat * 128 + row) * 72 + col]),
                   &src[gk + (size_t)row * DD + col]);
        }
        cp_commit();
    }

    {
        const size_t g0 = ((size_t)(b * TT + q0)) * DD + h * HD;
#pragma unroll
        for (int i = 0; i < 4; ++i) {
            int idx = tid + i * 256;
            int row = idx >> 3;
            int col = (idx & 7) * 8;
            *(int4*)&smQ[row * 72 + col] =
                *(const int4*)&g_q16[g0 + (size_t)row * DD + col];
        }
    }
    __syncthreads();

    uint32_t aQ[4][4];
    {
        const int arow = warp * 16 + (lane & 15);
#pragma unroll
        for (int c = 0; c < 4; ++c) {
            const int acol = c * 16 + ((lane >> 4) << 3);
            ldm_x4(smem_u32(&smQ[arow * 72 + acol]), aQ[c]);
        }
    }

    float oacc[8][4];
#pragma unroll
    for (int nt = 0; nt < 8; ++nt)
#pragma unroll
        for (int t = 0; t < 4; ++t) oacc[nt][t] = 0.f;
    float lacc[4] = {0.f, 0.f, 0.f, 0.f};
    float m0 = 0.f, m1 = 0.f;

    const int r0i = qbase + (lane >> 2);
    const int r1i = r0i + 8;

    for (int kt = 0, buf = 0; kt < nk; kt += 128, buf ^= 1) {
        cp_wait<0>();
        __syncthreads();
        __half* smB = buf ? smKV1 : smKV0;

        if (kt + 128 < nk) {
            const size_t gk = ((size_t)(b * TT + kt + 128)) * DD + h * HD;
            __half* dst = buf ? smKV0 : smKV1;
#pragma unroll
            for (int i = 0; i < 8; ++i) {
                int idx = tid + i * 256;
                int mat = idx >> 10;
                int w   = idx & 1023;
                int row = w >> 3;
                int col = (w & 7) * 8;
                const __half* src = mat ? g_v16 : g_k16;
                cp16ca(smem_u32(&dst[(mat * 128 + row) * 72 + col]),
                       &src[gk + (size_t)row * DD + col]);
            }
            cp_commit();
        }

#pragma unroll
        for (int sub = 0; sub < 2; ++sub) {
            const int ks0 = kt + sub * 64;
            if (ks0 > qbase) break;

            const __half* smK = smB + (sub * 64) * 72;
            const __half* smV = smB + (128 + sub * 64) * 72;

            float sacc[8][4];
#pragma unroll
            for (int nt = 0; nt < 8; ++nt)
#pragma unroll
                for (int t = 0; t < 4; ++t) sacc[nt][t] = 0.f;

            const int brow = ((lane >> 4) << 3) + (lane & 7);
#pragma unroll
            for (int c = 0; c < 4; ++c) {
                uint32_t bK[4][4];
                const int bcol = c * 16 + ((lane >> 3) & 1) * 8;
#pragma unroll
                for (int p = 0; p < 4; ++p)
                    ldm_x4(smem_u32(&smK[(p * 16 + brow) * 72 + bcol]), bK[p]);
#pragma unroll
                for (int nt = 0; nt < 8; ++nt) {
                    const int p = nt >> 1, q = (nt & 1) * 2;
                    mma_f16(sacc[nt], aQ[c], bK[p][q], bK[p][q + 1]);
                }
            }

            if (ks0 + 63 > qbase) {
#pragma unroll
                for (int nt = 0; nt < 8; ++nt) {
                    const int cb = ks0 + nt * 8 + (lane & 3) * 2;
                    if (cb     > r0i) sacc[nt][0] = -1e30f;
                    if (cb + 1 > r0i) sacc[nt][1] = -1e30f;
                    if (cb     > r1i) sacc[nt][2] = -1e30f;
                    if (cb + 1 > r1i) sacc[nt][3] = -1e30f;
                }
            }

            float tm0 = -1e30f, tm1 = -1e30f;
#pragma unroll
            for (int nt = 0; nt < 8; ++nt) {
                tm0 = fmaxf(tm0, fmaxf(sacc[nt][0], sacc[nt][1]));
                tm1 = fmaxf(tm1, fmaxf(sacc[nt][2], sacc[nt][3]));
            }
            tm0 = fmaxf(tm0, __shfl_xor_sync(0xffffffffu, tm0, 1));
            tm0 = fmaxf(tm0, __shfl_xor_sync(0xffffffffu, tm0, 2));
            tm1 = fmaxf(tm1, __shfl_xor_sync(0xffffffffu, tm1, 1));
            tm1 = fmaxf(tm1, __shfl_xor_sync(0xffffffffu, tm1, 2));

            const float mn0 = fmaxf(m0, tm0), mn1 = fmaxf(m1, tm1);
            if (__ballot_sync(0xffffffffu, (mn0 > m0) | (mn1 > m1))) {
                const float c0 = exp2f(m0 - mn0), c1 = exp2f(m1 - mn1);
                lacc[0] *= c0; lacc[1] *= c0; lacc[2] *= c1; lacc[3] *= c1;
#pragma unroll
                for (int nt = 0; nt < 8; ++nt) {
                    oacc[nt][0] *= c0; oacc[nt][1] *= c0;
                    oacc[nt][2] *= c1; oacc[nt][3] *= c1;
                }
                m0 = mn0; m1 = mn1;
            }

            const __half2 mh0 = __float2half2_rn(m0);
            const __half2 mh1 = __float2half2_rn(m1);
            uint32_t aP[4][4];
#pragma unroll
            for (int nt = 0; nt < 8; ++nt) {
                __half2 s01 = __floats2half2_rn(sacc[nt][0], sacc[nt][1]);
                __half2 s23 = __floats2half2_rn(sacc[nt][2], sacc[nt][3]);
                s01 = __hsub2(s01, mh0);
                s23 = __hsub2(s23, mh1);
                const int c = nt >> 1, rr = (nt & 1) * 2;
                aP[c][rr]     = ex2_f16x2(reinterpret_cast<uint32_t&>(s01));
                aP[c][rr + 1] = ex2_f16x2(reinterpret_cast<uint32_t&>(s23));
            }

#pragma unroll
            for (int c = 0; c < 4; ++c) {
                uint32_t bV[8][2];
                const int vrow = c * 16 + ((lane >> 3) & 1) * 8 + (lane & 7);
                const int vcol0 = (lane >> 4) << 3;
#pragma unroll
                for (int pr = 0; pr < 4; ++pr) {
                    uint32_t r[4];
                    ldm_x4_t(smem_u32(&smV[vrow * 72 + 16 * pr + vcol0]), r);
                    bV[2 * pr][0] = r[0]; bV[2 * pr][1] = r[1];
                    bV[2 * pr + 1][0] = r[2]; bV[2 * pr + 1][1] = r[3];
                }
#pragma unroll
                for (int nt = 0; nt < 8; ++nt)
                    mma_f16(oacc[nt], aP[c], bV[nt][0], bV[nt][1]);
                mma_f16(lacc, aP[c], H2_ONES, H2_ONES);
            }
        }
    }

    const float inv0 = 1.f / lacc[0], inv1 = 1.f / lacc[2];

#pragma unroll
    for (int nt = 0; nt < 8; ++nt) {
        const int col = h * HD + nt * 8 + (lane & 3) * 2;
        const size_t o0 = ((size_t)(b * TT + r0i)) * DD + col;
        const size_t o1 = ((size_t)(b * TT + r1i)) * DD + col;
        *(__half2*)&g_a16[o0] = __floats2half2_rn(oacc[nt][0] * inv0, oacc[nt][1] * inv0);
        *(__half2*)&g_a16[o1] = __floats2half2_rn(oacc[nt][2] * inv1, oacc[nt][3] * inv1);
    }
}

// ---------------------------------------------------------------------------
// Launch: inputs per metadata order: x, Wk, Wq, Wv, Wp, bp
// ---------------------------------------------------------------------------
extern "C" void kernel_launch(void* const* d_in, const int* in_sizes, int n_in,
                              void* d_out, int out_size)
{
    const float* x  = (const float*)d_in[0];
    const float* Wk = (const float*)d_in[1];
    const float* Wq = (const float*)d_in[2];
    const float* Wv = (const float*)d_in[3];
    const float* Wp = (const float*)d_in[4];
    const float* bp = (const float*)d_in[5];
    float* out = (float*)d_out;

    cudaFuncSetAttribute(gemm_nt_f16, cudaFuncAttributeMaxDynamicSharedMemorySize,
                         GEMM_SMEM);
    cudaFuncSetAttribute(flash_attn_f16, cudaFuncAttributeMaxDynamicSharedMemorySize,
                         FLASH_SMEM);

    // single merged convert (slot order: Wq, Wk, Wv, Wp), 8-way ILP
    cvt_all<<<TOT4 / (256 * 8), 256>>>(x, Wq, Wk, Wv, Wp);

    // fused QKV projection: N = 3072
    dim3 qkvGrid(3 * DD / 128, MM / 128);   // 24 x 64
    gemm_nt_f16<<<qkvGrid, 256, GEMM_SMEM>>>(0, 0, nullptr, nullptr, 1, 3 * DD);

    // flash attention -> g_a16
    dim3 fGrid(TT / 128, HH, BB);           // 16 x 16 x 4
    flash_attn_f16<<<fGrid, 256, FLASH_SMEM>>>();

    // output projection with bias -> d_out (fp32)
    dim3 oGrid(DD / 128, MM / 128);         // 8 x 64
    gemm_nt_f16<<<oGrid, 256, GEMM_SMEM>>>(1, 3, bp, out, 0, DD);
}